// round 3
// baseline (speedup 1.0000x reference)
#include <cuda_runtime.h>
#include <math.h>

#define LSEQ 4096
#define EMB  1024
#define NH   16
#define DH   64
#define QKV3 3072

// Scratch (allocation-free rule: device globals)
__device__ float g_qkv[LSEQ * QKV3];   // [L, 3E]
__device__ float g_attn[LSEQ * EMB];   // [L, E]

// ---------------------------------------------------------------------------
// C[m][n] = sum_k A[m][k] * B[n][k]   (A: [M,K] row-major, B: [N,K] row-major)
// 128x128 tile, BK=8, 256 threads, 8x8 microtile per thread.
// M, N multiples of 128; K multiple of 8.
// ---------------------------------------------------------------------------
__global__ __launch_bounds__(256) void gemm_nt(const float* __restrict__ A,
                                               const float* __restrict__ B,
                                               float* __restrict__ C,
                                               int M, int N, int K) {
    __shared__ float As[8 * 128];   // [k][m]
    __shared__ float Bs[8 * 128];   // [k][n]

    const int tid = threadIdx.x;
    const int tx = tid & 15;        // 0..15 -> n microtile
    const int ty = tid >> 4;        // 0..15 -> m microtile
    const int rbase = blockIdx.y * 128;
    const int cbase = blockIdx.x * 128;
    const int lr = tid >> 1;        // 0..127 row within tile
    const int lc = (tid & 1) << 2;  // 0 or 4: k sub-column (float4)

    float acc[8][8];
#pragma unroll
    for (int i = 0; i < 8; i++)
#pragma unroll
        for (int j = 0; j < 8; j++) acc[i][j] = 0.f;

    for (int k0 = 0; k0 < K; k0 += 8) {
        float4 a4 = *reinterpret_cast<const float4*>(&A[(size_t)(rbase + lr) * K + k0 + lc]);
        float4 b4 = *reinterpret_cast<const float4*>(&B[(size_t)(cbase + lr) * K + k0 + lc]);
        __syncthreads();   // previous compute must finish before overwrite
        As[(lc + 0) * 128 + lr] = a4.x;
        As[(lc + 1) * 128 + lr] = a4.y;
        As[(lc + 2) * 128 + lr] = a4.z;
        As[(lc + 3) * 128 + lr] = a4.w;
        Bs[(lc + 0) * 128 + lr] = b4.x;
        Bs[(lc + 1) * 128 + lr] = b4.y;
        Bs[(lc + 2) * 128 + lr] = b4.z;
        Bs[(lc + 3) * 128 + lr] = b4.w;
        __syncthreads();

#pragma unroll
        for (int kk = 0; kk < 8; kk++) {
            float a[8], b[8];
#pragma unroll
            for (int i = 0; i < 8; i++) a[i] = As[kk * 128 + ty * 8 + i];
#pragma unroll
            for (int j = 0; j < 8; j++) b[j] = Bs[kk * 128 + tx * 8 + j];
#pragma unroll
            for (int i = 0; i < 8; i++)
#pragma unroll
                for (int j = 0; j < 8; j++) acc[i][j] = fmaf(a[i], b[j], acc[i][j]);
        }
    }

#pragma unroll
    for (int i = 0; i < 8; i++) {
        size_t row = (size_t)(rbase + ty * 8 + i);
#pragma unroll
        for (int jv = 0; jv < 2; jv++) {
            float4 o;
            o.x = acc[i][jv * 4 + 0];
            o.y = acc[i][jv * 4 + 1];
            o.z = acc[i][jv * 4 + 2];
            o.w = acc[i][jv * 4 + 3];
            *reinterpret_cast<float4*>(&C[row * N + cbase + tx * 8 + jv * 4]) = o;
        }
    }
}

// ---------------------------------------------------------------------------
// Flash attention: one block = (head, 64-row Q tile). 256 threads.
// Q,K,V taken from fused qkv [L, 3E]; output [L, E] (pre-projection).
// Online softmax, fp32. Smem: Qs/Ks/Vs/Ps each [64][68] (pad 68 avoids
// the stride-64 16-way bank conflict on K/V column reads).
// ---------------------------------------------------------------------------
#define PAD 68
#define ATTN_SMEM (4 * 64 * PAD * 4)

__global__ __launch_bounds__(256) void attn_fwd(const float* __restrict__ qkv,
                                                float* __restrict__ out) {
    extern __shared__ float sm[];
    float* Qs = sm;                 // [64][PAD]
    float* Ks = sm + 64 * PAD;
    float* Vs = sm + 2 * 64 * PAD;
    float* Ps = sm + 3 * 64 * PAD;

    const int h   = blockIdx.y;
    const int q0  = blockIdx.x * 64;
    const int tid = threadIdx.x;
    const int tx  = tid & 15;       // 0..15 -> 4 cols each
    const int ty  = tid >> 4;       // 0..15 -> 4 rows each
    const int qoff = h * DH;
    const int koff = EMB + h * DH;
    const int voff = 2 * EMB + h * DH;

    // Load + scale Q tile (scale = DH^-0.5 = 0.125)
#pragma unroll
    for (int i = 0; i < 4; i++) {
        int lin = tid + i * 256;          // 0..1023
        int r = lin >> 4;
        int c = (lin & 15) << 2;
        float4 v = *reinterpret_cast<const float4*>(&qkv[(size_t)(q0 + r) * QKV3 + qoff + c]);
        float* dst = &Qs[r * PAD + c];
        dst[0] = v.x * 0.125f; dst[1] = v.y * 0.125f;
        dst[2] = v.z * 0.125f; dst[3] = v.w * 0.125f;
    }

    float m_i[4], l_i[4], acc[4][4];
#pragma unroll
    for (int i = 0; i < 4; i++) {
        m_i[i] = -1e30f;
        l_i[i] = 0.f;
#pragma unroll
        for (int j = 0; j < 4; j++) acc[i][j] = 0.f;
    }

    for (int kt = 0; kt < LSEQ / 64; kt++) {
        __syncthreads();   // previous P*V done; Q visible on first iter
#pragma unroll
        for (int i = 0; i < 4; i++) {
            int lin = tid + i * 256;
            int r = lin >> 4;
            int c = (lin & 15) << 2;
            size_t grow = (size_t)(kt * 64 + r) * QKV3;
            float4 k4 = *reinterpret_cast<const float4*>(&qkv[grow + koff + c]);
            float4 v4 = *reinterpret_cast<const float4*>(&qkv[grow + voff + c]);
            float* kd = &Ks[r * PAD + c];
            kd[0] = k4.x; kd[1] = k4.y; kd[2] = k4.z; kd[3] = k4.w;
            float* vd = &Vs[r * PAD + c];
            vd[0] = v4.x; vd[1] = v4.y; vd[2] = v4.z; vd[3] = v4.w;
        }
        __syncthreads();

        // S = (Q*scale) K^T  -- 4x4 per thread
        float s[4][4];
#pragma unroll
        for (int i = 0; i < 4; i++)
#pragma unroll
            for (int j = 0; j < 4; j++) s[i][j] = 0.f;

#pragma unroll 8
        for (int d = 0; d < DH; d++) {
            float qv[4], kv[4];
#pragma unroll
            for (int i = 0; i < 4; i++) qv[i] = Qs[(ty * 4 + i) * PAD + d];
#pragma unroll
            for (int j = 0; j < 4; j++) kv[j] = Ks[(tx * 4 + j) * PAD + d];
#pragma unroll
            for (int i = 0; i < 4; i++)
#pragma unroll
                for (int j = 0; j < 4; j++) s[i][j] = fmaf(qv[i], kv[j], s[i][j]);
        }

        // Online softmax. Row r=ty*4+i is owned by lanes tx=0..15 within a
        // 16-lane group (offsets 1,2,4,8 stay inside the group).
#pragma unroll
        for (int i = 0; i < 4; i++) {
            float mt = fmaxf(fmaxf(s[i][0], s[i][1]), fmaxf(s[i][2], s[i][3]));
#pragma unroll
            for (int off = 8; off >= 1; off >>= 1)
                mt = fmaxf(mt, __shfl_xor_sync(0xffffffffu, mt, off));
            float mnew = fmaxf(m_i[i], mt);
            float corr = __expf(m_i[i] - mnew);
            float lsum = 0.f;
#pragma unroll
            for (int j = 0; j < 4; j++) {
                s[i][j] = __expf(s[i][j] - mnew);
                lsum += s[i][j];
            }
#pragma unroll
            for (int off = 8; off >= 1; off >>= 1)
                lsum += __shfl_xor_sync(0xffffffffu, lsum, off);
            l_i[i] = l_i[i] * corr + lsum;
            m_i[i] = mnew;
#pragma unroll
            for (int j = 0; j < 4; j++) {
                acc[i][j] *= corr;
                Ps[(ty * 4 + i) * PAD + tx * 4 + j] = s[i][j];
            }
        }
        __syncthreads();

        // O += P V
#pragma unroll 8
        for (int mm = 0; mm < 64; mm++) {
            float pv[4], vv[4];
#pragma unroll
            for (int i = 0; i < 4; i++) pv[i] = Ps[(ty * 4 + i) * PAD + mm];
#pragma unroll
            for (int j = 0; j < 4; j++) vv[j] = Vs[mm * PAD + tx * 4 + j];
#pragma unroll
            for (int i = 0; i < 4; i++)
#pragma unroll
                for (int j = 0; j < 4; j++) acc[i][j] = fmaf(pv[i], vv[j], acc[i][j]);
        }
    }

#pragma unroll
    for (int i = 0; i < 4; i++) {
        float inv = 1.0f / l_i[i];
#pragma unroll
        for (int j = 0; j < 4; j++)
            out[(size_t)(q0 + ty * 4 + i) * EMB + h * DH + tx * 4 + j] = acc[i][j] * inv;
    }
}

// ---------------------------------------------------------------------------
extern "C" void kernel_launch(void* const* d_in, const int* in_sizes, int n_in,
                              void* d_out, int out_size) {
    const float* x     = (const float*)d_in[0];   // [L, 1, E]
    const float* w_qkv = (const float*)d_in[1];   // [3E, E]
    const float* w_out = (const float*)d_in[2];   // [E, E]
    float* out = (float*)d_out;                   // [L, 1, E]

    float *qkv, *attn;
    cudaGetSymbolAddress((void**)&qkv, g_qkv);
    cudaGetSymbolAddress((void**)&attn, g_attn);

    // 1) QKV projection: [L,E] @ [3E,E]^T -> [L,3E]
    gemm_nt<<<dim3(QKV3 / 128, LSEQ / 128), 256>>>(x, w_qkv, qkv, LSEQ, QKV3, EMB);

    // 2) Attention
    cudaFuncSetAttribute(attn_fwd, cudaFuncAttributeMaxDynamicSharedMemorySize, ATTN_SMEM);
    attn_fwd<<<dim3(LSEQ / 64, NH), 256, ATTN_SMEM>>>(qkv, attn);

    // 3) Output projection: [L,E] @ [E,E]^T -> [L,E]
    gemm_nt<<<dim3(EMB / 128, LSEQ / 128), 256>>>(attn, w_out, out, LSEQ, EMB, EMB);
}

// round 5
// speedup vs baseline: 2.0481x; 2.0481x over previous
#include <cuda_runtime.h>
#include <cstdint>
#include <math.h>

#define LSEQ 4096
#define EMB  1024
#define NH   16
#define DH   64
#define QKV3 3072

// Scratch (allocation-free rule: device globals)
__device__ float g_qkv[LSEQ * QKV3];   // [L, 3E]
__device__ float g_attn[LSEQ * EMB];   // [L, E]

// ===========================================================================
// Helpers (non-'a' PTX only: ldmatrix / mma.sync tf32 / cvt.rna.tf32)
// ===========================================================================
__device__ __forceinline__ uint32_t smem_u32(const void* p) {
    uint32_t a;
    asm("{ .reg .u64 t; cvta.to.shared.u64 t, %1; cvt.u32.u64 %0, t; }" : "=r"(a) : "l"(p));
    return a;
}
__device__ __forceinline__ uint32_t f2tf32(float f) {
    uint32_t r; asm("cvt.rna.tf32.f32 %0, %1;" : "=r"(r) : "f"(f)); return r;
}
__device__ __forceinline__ void ldmatrix_x4(uint32_t& r0, uint32_t& r1, uint32_t& r2, uint32_t& r3,
                                            uint32_t addr) {
    asm volatile("ldmatrix.sync.aligned.m8n8.x4.shared.b16 {%0,%1,%2,%3}, [%4];"
                 : "=r"(r0), "=r"(r1), "=r"(r2), "=r"(r3) : "r"(addr));
}
__device__ __forceinline__ void ldmatrix_x2(uint32_t& r0, uint32_t& r1, uint32_t addr) {
    asm volatile("ldmatrix.sync.aligned.m8n8.x2.shared.b16 {%0,%1}, [%2];"
                 : "=r"(r0), "=r"(r1) : "r"(addr));
}
__device__ __forceinline__ void mma_tf32(float& c0, float& c1, float& c2, float& c3,
                                         uint32_t a0, uint32_t a1, uint32_t a2, uint32_t a3,
                                         uint32_t b0, uint32_t b1) {
    asm volatile(
        "mma.sync.aligned.m16n8k8.row.col.f32.tf32.tf32.f32 "
        "{%0,%1,%2,%3}, {%4,%5,%6,%7}, {%8,%9}, {%0,%1,%2,%3};"
        : "+f"(c0), "+f"(c1), "+f"(c2), "+f"(c3)
        : "r"(a0), "r"(a1), "r"(a2), "r"(a3), "r"(b0), "r"(b1));
}

// ===========================================================================
// Tensor-core tf32 GEMM: C[m][n] = sum_k A[m][k]*B[n][k]
// A: [M,K] row-major, B: [N,K] row-major. 128x128 CTA tile, BK=32.
// 8 warps as 2(m) x 4(n); warp tile 64x32 = 4x4 m16n8k8 fragments.
// Smem rows padded to 36 floats (stride 144B -> ldmatrix conflict-free).
// ===========================================================================
#define GPAD 36

__global__ __launch_bounds__(256) void gemm_mma(const float* __restrict__ A,
                                                const float* __restrict__ B,
                                                float* __restrict__ C,
                                                int M, int N, int K) {
    __shared__ float As[128 * GPAD];
    __shared__ float Bs[128 * GPAD];

    const int tid = threadIdx.x;
    const int t = tid & 31;
    const int wid = tid >> 5;
    const int wm = wid >> 2;       // 0..1 -> 64 rows each
    const int wn = wid & 3;        // 0..3 -> 32 cols each
    const int rbase = blockIdx.y * 128;
    const int cbase = blockIdx.x * 128;
    const int nchunks = K >> 5;

    const uint32_t As_b = smem_u32(As);
    const uint32_t Bs_b = smem_u32(Bs);

    // ldmatrix source addresses (byte offsets into smem, per thread)
    const int a_rl = (t & 7) + ((t >> 3) & 1) * 8;     // row within 16-row frag
    const int a_cb = ((t >> 4) & 1) * 16;              // byte offset (tf32 col 0 / 4)
    const int b_rl = (t & 7);                          // n-row within 8-row frag
    const int b_cb = ((t >> 3) & 1) * 16;

    // global load mapping: 4 float4 per tensor per chunk per thread
    // fi = tid + i*256 -> row = fi>>3 (0..127), col4 = (fi&7)*4
    float c[4][4][4];
#pragma unroll
    for (int mf = 0; mf < 4; mf++)
#pragma unroll
        for (int nf = 0; nf < 4; nf++)
#pragma unroll
            for (int v = 0; v < 4; v++) c[mf][nf][v] = 0.f;

    float4 pa[4], pb[4];
    {
        const float* Ag = A + (size_t)rbase * K;
        const float* Bg = B + (size_t)cbase * K;
#pragma unroll
        for (int i = 0; i < 4; i++) {
            int fi = tid + i * 256;
            int row = fi >> 3, c4 = (fi & 7) << 2;
            pa[i] = *reinterpret_cast<const float4*>(Ag + (size_t)row * K + c4);
            pb[i] = *reinterpret_cast<const float4*>(Bg + (size_t)row * K + c4);
        }
    }

    for (int ck = 0; ck < nchunks; ck++) {
        // store prefetched chunk (converted to tf32 bits)
#pragma unroll
        for (int i = 0; i < 4; i++) {
            int fi = tid + i * 256;
            int row = fi >> 3, c4 = (fi & 7) << 2;
            float4 av, bv;
            av.x = __uint_as_float(f2tf32(pa[i].x));
            av.y = __uint_as_float(f2tf32(pa[i].y));
            av.z = __uint_as_float(f2tf32(pa[i].z));
            av.w = __uint_as_float(f2tf32(pa[i].w));
            bv.x = __uint_as_float(f2tf32(pb[i].x));
            bv.y = __uint_as_float(f2tf32(pb[i].y));
            bv.z = __uint_as_float(f2tf32(pb[i].z));
            bv.w = __uint_as_float(f2tf32(pb[i].w));
            *reinterpret_cast<float4*>(&As[row * GPAD + c4]) = av;
            *reinterpret_cast<float4*>(&Bs[row * GPAD + c4]) = bv;
        }
        __syncthreads();

        // prefetch next chunk
        if (ck + 1 < nchunks) {
            const float* Ag = A + (size_t)rbase * K + (ck + 1) * 32;
            const float* Bg = B + (size_t)cbase * K + (ck + 1) * 32;
#pragma unroll
            for (int i = 0; i < 4; i++) {
                int fi = tid + i * 256;
                int row = fi >> 3, c4 = (fi & 7) << 2;
                pa[i] = *reinterpret_cast<const float4*>(Ag + (size_t)row * K + c4);
                pb[i] = *reinterpret_cast<const float4*>(Bg + (size_t)row * K + c4);
            }
        }

        // compute: 4 k-steps of 8
#pragma unroll
        for (int ks = 0; ks < 4; ks++) {
            uint32_t af[4][4], bf[4][2];
#pragma unroll
            for (int mf = 0; mf < 4; mf++) {
                int row = wm * 64 + mf * 16 + a_rl;
                uint32_t addr = As_b + (uint32_t)(row * GPAD * 4 + ks * 32 + a_cb);
                ldmatrix_x4(af[mf][0], af[mf][1], af[mf][2], af[mf][3], addr);
            }
#pragma unroll
            for (int nf = 0; nf < 4; nf++) {
                int row = wn * 32 + nf * 8 + b_rl;
                uint32_t addr = Bs_b + (uint32_t)(row * GPAD * 4 + ks * 32 + b_cb);
                ldmatrix_x2(bf[nf][0], bf[nf][1], addr);
            }
#pragma unroll
            for (int mf = 0; mf < 4; mf++)
#pragma unroll
                for (int nf = 0; nf < 4; nf++)
                    mma_tf32(c[mf][nf][0], c[mf][nf][1], c[mf][nf][2], c[mf][nf][3],
                             af[mf][0], af[mf][1], af[mf][2], af[mf][3],
                             bf[nf][0], bf[nf][1]);
        }
        __syncthreads();
    }

    // epilogue: c0,c1 -> (row, col..col+1); c2,c3 -> (row+8, ...)
    const int g = t >> 2;          // groupID
    const int tg = t & 3;          // threadID in group
#pragma unroll
    for (int mf = 0; mf < 4; mf++) {
        int row0 = rbase + wm * 64 + mf * 16 + g;
#pragma unroll
        for (int nf = 0; nf < 4; nf++) {
            int col = cbase + wn * 32 + nf * 8 + 2 * tg;
            float2 lo = make_float2(c[mf][nf][0], c[mf][nf][1]);
            float2 hi = make_float2(c[mf][nf][2], c[mf][nf][3]);
            *reinterpret_cast<float2*>(&C[(size_t)row0 * N + col]) = lo;
            *reinterpret_cast<float2*>(&C[(size_t)(row0 + 8) * N + col]) = hi;
        }
    }
}

// ===========================================================================
// Flash attention (SIMT fp32): block = (head, 128-row Q tile), 256 threads.
// 8x4 microtile; Q/K stored d-major (transposed) in smem so lane-varying
// reads are contiguous float4 (conflict-free); P reads are broadcasts.
// ===========================================================================
#define BM 128
#define BN 64
#define QPAD 132
#define KPAD 68
#define OFF_Q 0
#define OFF_K (64 * QPAD)
#define OFF_V (OFF_K + 64 * KPAD)
#define OFF_P (OFF_V + 64 * KPAD)
#define ATTN_SMEM ((OFF_P + BM * KPAD) * 4)

__global__ __launch_bounds__(256) void attn_fwd2(const float* __restrict__ qkv,
                                                 float* __restrict__ out) {
    extern __shared__ float sm[];
    float* Qs = sm + OFF_Q;   // [64][QPAD]  d-major
    float* Ks = sm + OFF_K;   // [64][KPAD]  d-major
    float* Vs = sm + OFF_V;   // [64][KPAD]  row-major
    float* Ps = sm + OFF_P;   // [128][KPAD] row-major

    const int h = blockIdx.y;
    const int q0 = blockIdx.x * BM;
    const int tid = threadIdx.x;
    const int tx = tid & 15;   // 4 kv-cols each
    const int ty = tid >> 4;   // 8 q-rows each
    const int qoff = h * DH;
    const int koff = EMB + h * DH;
    const int voff = 2 * EMB + h * DH;

    // Load Q (scaled) transposed: Qs[d][r]
#pragma unroll
    for (int i = 0; i < 8; i++) {
        int lin = tid + i * 256;      // 0..2047 float4 slots (128 rows x 16)
        int r = lin >> 4;
        int c = (lin & 15) << 2;
        float4 v = *reinterpret_cast<const float4*>(&qkv[(size_t)(q0 + r) * QKV3 + qoff + c]);
        Qs[(c + 0) * QPAD + r] = v.x * 0.125f;
        Qs[(c + 1) * QPAD + r] = v.y * 0.125f;
        Qs[(c + 2) * QPAD + r] = v.z * 0.125f;
        Qs[(c + 3) * QPAD + r] = v.w * 0.125f;
    }

    float m_i[8], l_i[8], acc[8][4];
#pragma unroll
    for (int i = 0; i < 8; i++) {
        m_i[i] = -1e30f;
        l_i[i] = 0.f;
#pragma unroll
        for (int j = 0; j < 4; j++) acc[i][j] = 0.f;
    }

    for (int kt = 0; kt < LSEQ / BN; kt++) {
        __syncthreads();   // prev PV done (and Q visible on first iter)
#pragma unroll
        for (int i = 0; i < 4; i++) {
            int lin = tid + i * 256;  // 0..1023 (64 rows x 16)
            int r = lin >> 4;
            int c = (lin & 15) << 2;
            size_t grow = (size_t)(kt * BN + r) * QKV3;
            float4 k4 = *reinterpret_cast<const float4*>(&qkv[grow + koff + c]);
            Ks[(c + 0) * KPAD + r] = k4.x;
            Ks[(c + 1) * KPAD + r] = k4.y;
            Ks[(c + 2) * KPAD + r] = k4.z;
            Ks[(c + 3) * KPAD + r] = k4.w;
            float4 v4 = *reinterpret_cast<const float4*>(&qkv[grow + voff + c]);
            *reinterpret_cast<float4*>(&Vs[r * KPAD + c]) = v4;
        }
        __syncthreads();

        // S = (Q*scale) K^T, 8x4 per thread
        float s[8][4];
#pragma unroll
        for (int i = 0; i < 8; i++)
#pragma unroll
            for (int j = 0; j < 4; j++) s[i][j] = 0.f;

#pragma unroll 4
        for (int d = 0; d < DH; d++) {
            float4 kf = *reinterpret_cast<const float4*>(&Ks[d * KPAD + tx * 4]);
            float4 qa = *reinterpret_cast<const float4*>(&Qs[d * QPAD + ty * 8]);
            float4 qb = *reinterpret_cast<const float4*>(&Qs[d * QPAD + ty * 8 + 4]);
            float qv[8] = {qa.x, qa.y, qa.z, qa.w, qb.x, qb.y, qb.z, qb.w};
            float kv[4] = {kf.x, kf.y, kf.z, kf.w};
#pragma unroll
            for (int i = 0; i < 8; i++)
#pragma unroll
                for (int j = 0; j < 4; j++) s[i][j] = fmaf(qv[i], kv[j], s[i][j]);
        }

        // Online softmax: row ty*8+i spans the 16 tx lanes (xor 1,2,4,8 stays in group)
#pragma unroll
        for (int i = 0; i < 8; i++) {
            float mt = fmaxf(fmaxf(s[i][0], s[i][1]), fmaxf(s[i][2], s[i][3]));
#pragma unroll
            for (int off = 8; off >= 1; off >>= 1)
                mt = fmaxf(mt, __shfl_xor_sync(0xffffffffu, mt, off));
            float mnew = fmaxf(m_i[i], mt);
            float corr = __expf(m_i[i] - mnew);
            float lsum = 0.f;
#pragma unroll
            for (int j = 0; j < 4; j++) {
                s[i][j] = __expf(s[i][j] - mnew);
                lsum += s[i][j];
            }
#pragma unroll
            for (int off = 8; off >= 1; off >>= 1)
                lsum += __shfl_xor_sync(0xffffffffu, lsum, off);
            l_i[i] = l_i[i] * corr + lsum;
            m_i[i] = mnew;
#pragma unroll
            for (int j = 0; j < 4; j++) acc[i][j] *= corr;
            float4 pw = make_float4(s[i][0], s[i][1], s[i][2], s[i][3]);
            *reinterpret_cast<float4*>(&Ps[(ty * 8 + i) * KPAD + tx * 4]) = pw;
        }
        __syncthreads();

        // O += P V  (P reads broadcast, V reads contiguous)
#pragma unroll 2
        for (int mm = 0; mm < BN; mm += 4) {
            float4 v0 = *reinterpret_cast<const float4*>(&Vs[(mm + 0) * KPAD + tx * 4]);
            float4 v1 = *reinterpret_cast<const float4*>(&Vs[(mm + 1) * KPAD + tx * 4]);
            float4 v2 = *reinterpret_cast<const float4*>(&Vs[(mm + 2) * KPAD + tx * 4]);
            float4 v3 = *reinterpret_cast<const float4*>(&Vs[(mm + 3) * KPAD + tx * 4]);
#pragma unroll
            for (int i = 0; i < 8; i++) {
                float4 p = *reinterpret_cast<const float4*>(&Ps[(ty * 8 + i) * KPAD + mm]);
                acc[i][0] = fmaf(p.x, v0.x, acc[i][0]);
                acc[i][1] = fmaf(p.x, v0.y, acc[i][1]);
                acc[i][2] = fmaf(p.x, v0.z, acc[i][2]);
                acc[i][3] = fmaf(p.x, v0.w, acc[i][3]);
                acc[i][0] = fmaf(p.y, v1.x, acc[i][0]);
                acc[i][1] = fmaf(p.y, v1.y, acc[i][1]);
                acc[i][2] = fmaf(p.y, v1.z, acc[i][2]);
                acc[i][3] = fmaf(p.y, v1.w, acc[i][3]);
                acc[i][0] = fmaf(p.z, v2.x, acc[i][0]);
                acc[i][1] = fmaf(p.z, v2.y, acc[i][1]);
                acc[i][2] = fmaf(p.z, v2.z, acc[i][2]);
                acc[i][3] = fmaf(p.z, v2.w, acc[i][3]);
                acc[i][0] = fmaf(p.w, v3.x, acc[i][0]);
                acc[i][1] = fmaf(p.w, v3.y, acc[i][1]);
                acc[i][2] = fmaf(p.w, v3.z, acc[i][2]);
                acc[i][3] = fmaf(p.w, v3.w, acc[i][3]);
            }
        }
    }

#pragma unroll
    for (int i = 0; i < 8; i++) {
        float inv = 1.0f / l_i[i];
        float4 o;
        o.x = acc[i][0] * inv;
        o.y = acc[i][1] * inv;
        o.z = acc[i][2] * inv;
        o.w = acc[i][3] * inv;
        *reinterpret_cast<float4*>(&out[(size_t)(q0 + ty * 8 + i) * EMB + h * DH + tx * 4]) = o;
    }
}

// ===========================================================================
extern "C" void kernel_launch(void* const* d_in, const int* in_sizes, int n_in,
                              void* d_out, int out_size) {
    const float* x     = (const float*)d_in[0];   // [L, 1, E]
    const float* w_qkv = (const float*)d_in[1];   // [3E, E]
    const float* w_out = (const float*)d_in[2];   // [E, E]
    float* out = (float*)d_out;                   // [L, 1, E]

    float *qkv, *attn;
    cudaGetSymbolAddress((void**)&qkv, g_qkv);
    cudaGetSymbolAddress((void**)&attn, g_attn);

    cudaFuncSetAttribute(attn_fwd2, cudaFuncAttributeMaxDynamicSharedMemorySize, ATTN_SMEM);

    // 1) QKV projection: [L,E] @ [3E,E]^T -> [L,3E]  (mma.sync tf32)
    gemm_mma<<<dim3(QKV3 / 128, LSEQ / 128), 256>>>(x, w_qkv, qkv, LSEQ, QKV3, EMB);

    // 2) Attention (SIMT fp32, 128x64 tiles, transposed K/Q smem)
    attn_fwd2<<<dim3(LSEQ / BM, NH), 256, ATTN_SMEM>>>(qkv, attn);

    // 3) Output projection: [L,E] @ [E,E]^T -> [L,E]  (mma.sync tf32)
    gemm_mma<<<dim3(EMB / 128, LSEQ / 128), 256>>>(attn, w_out, out, LSEQ, EMB, EMB);
}

// round 7
// speedup vs baseline: 4.2351x; 2.0678x over previous
#include <cuda_runtime.h>
#include <cuda_bf16.h>
#include <cstdint>
#include <math.h>

#define LSEQ 4096
#define EMB  1024
#define NH   16
#define DH   64
#define QKV3 3072

// Scratch (allocation-free rule: device globals)
__device__ float g_qkv[LSEQ * QKV3];   // [L, 3E]
__device__ float g_attn[LSEQ * EMB];   // [L, E]
__device__ __nv_bfloat16 g_qh[LSEQ * EMB], g_ql[LSEQ * EMB];   // Q*scale hi/lo [L,E]
__device__ __nv_bfloat16 g_kh[LSEQ * EMB], g_kl[LSEQ * EMB];   // K hi/lo [L,E]
__device__ __nv_bfloat16 g_vth[EMB * LSEQ], g_vtl[EMB * LSEQ]; // V^T hi/lo [E,L]

// ===========================================================================
// PTX helpers (non-'a' features only: ldmatrix / mma.sync / cvt)
// ===========================================================================
__device__ __forceinline__ uint32_t smem_u32(const void* p) {
    uint32_t a;
    asm("{ .reg .u64 t; cvta.to.shared.u64 t, %1; cvt.u32.u64 %0, t; }" : "=r"(a) : "l"(p));
    return a;
}
__device__ __forceinline__ uint32_t f2tf32(float f) {
    uint32_t r; asm("cvt.rna.tf32.f32 %0, %1;" : "=r"(r) : "f"(f)); return r;
}
__device__ __forceinline__ void ldmatrix_x4(uint32_t& r0, uint32_t& r1, uint32_t& r2, uint32_t& r3,
                                            uint32_t addr) {
    asm volatile("ldmatrix.sync.aligned.m8n8.x4.shared.b16 {%0,%1,%2,%3}, [%4];"
                 : "=r"(r0), "=r"(r1), "=r"(r2), "=r"(r3) : "r"(addr));
}
__device__ __forceinline__ void ldmatrix_x2(uint32_t& r0, uint32_t& r1, uint32_t addr) {
    asm volatile("ldmatrix.sync.aligned.m8n8.x2.shared.b16 {%0,%1}, [%2];"
                 : "=r"(r0), "=r"(r1) : "r"(addr));
}
__device__ __forceinline__ void mma_tf32(float& c0, float& c1, float& c2, float& c3,
                                         uint32_t a0, uint32_t a1, uint32_t a2, uint32_t a3,
                                         uint32_t b0, uint32_t b1) {
    asm volatile(
        "mma.sync.aligned.m16n8k8.row.col.f32.tf32.tf32.f32 "
        "{%0,%1,%2,%3}, {%4,%5,%6,%7}, {%8,%9}, {%0,%1,%2,%3};"
        : "+f"(c0), "+f"(c1), "+f"(c2), "+f"(c3)
        : "r"(a0), "r"(a1), "r"(a2), "r"(a3), "r"(b0), "r"(b1));
}
__device__ __forceinline__ void mma_bf16(float* c,
                                         uint32_t a0, uint32_t a1, uint32_t a2, uint32_t a3,
                                         uint32_t b0, uint32_t b1) {
    asm volatile(
        "mma.sync.aligned.m16n8k16.row.col.f32.bf16.bf16.f32 "
        "{%0,%1,%2,%3}, {%4,%5,%6,%7}, {%8,%9}, {%0,%1,%2,%3};"
        : "+f"(c[0]), "+f"(c[1]), "+f"(c[2]), "+f"(c[3])
        : "r"(a0), "r"(a1), "r"(a2), "r"(a3), "r"(b0), "r"(b1));
}
__device__ __forceinline__ void bsplit(float x, __nv_bfloat16& h, __nv_bfloat16& l) {
    h = __float2bfloat16(x);
    l = __float2bfloat16(x - __bfloat162float(h));
}
__device__ __forceinline__ void bsplit2(float x0, float x1, uint32_t& hi, uint32_t& lo) {
    __nv_bfloat16 h0, l0, h1, l1;
    bsplit(x0, h0, l0);
    bsplit(x1, h1, l1);
    hi = ((uint32_t)__bfloat16_as_ushort(h1) << 16) | (uint32_t)__bfloat16_as_ushort(h0);
    lo = ((uint32_t)__bfloat16_as_ushort(l1) << 16) | (uint32_t)__bfloat16_as_ushort(l0);
}

// ===========================================================================
// Tensor-core tf32 GEMM (unchanged from R5): C[m][n] = sum_k A[m][k]*B[n][k]
// ===========================================================================
#define GPAD 36

__global__ __launch_bounds__(256) void gemm_mma(const float* __restrict__ A,
                                                const float* __restrict__ B,
                                                float* __restrict__ C,
                                                int M, int N, int K) {
    __shared__ float As[128 * GPAD];
    __shared__ float Bs[128 * GPAD];

    const int tid = threadIdx.x;
    const int t = tid & 31;
    const int wid = tid >> 5;
    const int wm = wid >> 2;
    const int wn = wid & 3;
    const int rbase = blockIdx.y * 128;
    const int cbase = blockIdx.x * 128;
    const int nchunks = K >> 5;

    const uint32_t As_b = smem_u32(As);
    const uint32_t Bs_b = smem_u32(Bs);

    const int a_rl = (t & 7) + ((t >> 3) & 1) * 8;
    const int a_cb = ((t >> 4) & 1) * 16;
    const int b_rl = (t & 7);
    const int b_cb = ((t >> 3) & 1) * 16;

    float c[4][4][4];
#pragma unroll
    for (int mf = 0; mf < 4; mf++)
#pragma unroll
        for (int nf = 0; nf < 4; nf++)
#pragma unroll
            for (int v = 0; v < 4; v++) c[mf][nf][v] = 0.f;

    float4 pa[4], pb[4];
    {
        const float* Ag = A + (size_t)rbase * K;
        const float* Bg = B + (size_t)cbase * K;
#pragma unroll
        for (int i = 0; i < 4; i++) {
            int fi = tid + i * 256;
            int row = fi >> 3, c4 = (fi & 7) << 2;
            pa[i] = *reinterpret_cast<const float4*>(Ag + (size_t)row * K + c4);
            pb[i] = *reinterpret_cast<const float4*>(Bg + (size_t)row * K + c4);
        }
    }

    for (int ck = 0; ck < nchunks; ck++) {
#pragma unroll
        for (int i = 0; i < 4; i++) {
            int fi = tid + i * 256;
            int row = fi >> 3, c4 = (fi & 7) << 2;
            float4 av, bv;
            av.x = __uint_as_float(f2tf32(pa[i].x));
            av.y = __uint_as_float(f2tf32(pa[i].y));
            av.z = __uint_as_float(f2tf32(pa[i].z));
            av.w = __uint_as_float(f2tf32(pa[i].w));
            bv.x = __uint_as_float(f2tf32(pb[i].x));
            bv.y = __uint_as_float(f2tf32(pb[i].y));
            bv.z = __uint_as_float(f2tf32(pb[i].z));
            bv.w = __uint_as_float(f2tf32(pb[i].w));
            *reinterpret_cast<float4*>(&As[row * GPAD + c4]) = av;
            *reinterpret_cast<float4*>(&Bs[row * GPAD + c4]) = bv;
        }
        __syncthreads();

        if (ck + 1 < nchunks) {
            const float* Ag = A + (size_t)rbase * K + (ck + 1) * 32;
            const float* Bg = B + (size_t)cbase * K + (ck + 1) * 32;
#pragma unroll
            for (int i = 0; i < 4; i++) {
                int fi = tid + i * 256;
                int row = fi >> 3, c4 = (fi & 7) << 2;
                pa[i] = *reinterpret_cast<const float4*>(Ag + (size_t)row * K + c4);
                pb[i] = *reinterpret_cast<const float4*>(Bg + (size_t)row * K + c4);
            }
        }

#pragma unroll
        for (int ks = 0; ks < 4; ks++) {
            uint32_t af[4][4], bf[4][2];
#pragma unroll
            for (int mf = 0; mf < 4; mf++) {
                int row = wm * 64 + mf * 16 + a_rl;
                uint32_t addr = As_b + (uint32_t)(row * GPAD * 4 + ks * 32 + a_cb);
                ldmatrix_x4(af[mf][0], af[mf][1], af[mf][2], af[mf][3], addr);
            }
#pragma unroll
            for (int nf = 0; nf < 4; nf++) {
                int row = wn * 32 + nf * 8 + b_rl;
                uint32_t addr = Bs_b + (uint32_t)(row * GPAD * 4 + ks * 32 + b_cb);
                ldmatrix_x2(bf[nf][0], bf[nf][1], addr);
            }
#pragma unroll
            for (int mf = 0; mf < 4; mf++)
#pragma unroll
                for (int nf = 0; nf < 4; nf++)
                    mma_tf32(c[mf][nf][0], c[mf][nf][1], c[mf][nf][2], c[mf][nf][3],
                             af[mf][0], af[mf][1], af[mf][2], af[mf][3],
                             bf[nf][0], bf[nf][1]);
        }
        __syncthreads();
    }

    const int g = t >> 2;
    const int tg = t & 3;
#pragma unroll
    for (int mf = 0; mf < 4; mf++) {
        int row0 = rbase + wm * 64 + mf * 16 + g;
#pragma unroll
        for (int nf = 0; nf < 4; nf++) {
            int col = cbase + wn * 32 + nf * 8 + 2 * tg;
            float2 lo = make_float2(c[mf][nf][0], c[mf][nf][1]);
            float2 hi = make_float2(c[mf][nf][2], c[mf][nf][3]);
            *reinterpret_cast<float2*>(&C[(size_t)row0 * N + col]) = lo;
            *reinterpret_cast<float2*>(&C[(size_t)(row0 + 8) * N + col]) = hi;
        }
    }
}

// ===========================================================================
// Prep: split Q (scaled) and K into bf16 hi/lo
// ===========================================================================
__global__ __launch_bounds__(256) void prep_qk(const float* __restrict__ qkv,
                                               __nv_bfloat16* __restrict__ qh,
                                               __nv_bfloat16* __restrict__ ql,
                                               __nv_bfloat16* __restrict__ kh,
                                               __nv_bfloat16* __restrict__ kl) {
    int idx = blockIdx.x * 256 + threadIdx.x;   // over L*E/4
    int l = idx >> 8;                            // E/4 = 256 per row
    int e = (idx & 255) << 2;
    float4 q = *reinterpret_cast<const float4*>(qkv + (size_t)l * QKV3 + e);
    float4 k = *reinterpret_cast<const float4*>(qkv + (size_t)l * QKV3 + EMB + e);
    size_t o = (size_t)l * EMB + e;
    float qs[4] = {q.x * 0.125f, q.y * 0.125f, q.z * 0.125f, q.w * 0.125f};
    float ks[4] = {k.x, k.y, k.z, k.w};
#pragma unroll
    for (int j = 0; j < 4; j++) {
        __nv_bfloat16 h, lo;
        bsplit(qs[j], h, lo);
        qh[o + j] = h; ql[o + j] = lo;
        bsplit(ks[j], h, lo);
        kh[o + j] = h; kl[o + j] = lo;
    }
}

// Prep: transpose V into [E, L] and split into bf16 hi/lo
__global__ __launch_bounds__(256) void prep_vt(const float* __restrict__ qkv,
                                               __nv_bfloat16* __restrict__ vth,
                                               __nv_bfloat16* __restrict__ vtl) {
    __shared__ float tile[32][33];
    const int e0 = blockIdx.x * 32;
    const int l0 = blockIdx.y * 32;
    const int tx = threadIdx.x, ty = threadIdx.y;   // (32, 8)
#pragma unroll
    for (int j = 0; j < 4; j++)
        tile[ty * 4 + j][tx] = qkv[(size_t)(l0 + ty * 4 + j) * QKV3 + 2 * EMB + e0 + tx];
    __syncthreads();
#pragma unroll
    for (int j = 0; j < 4; j++) {
        float v = tile[tx][ty * 4 + j];      // = V[l0+tx][e0+ty*4+j]
        __nv_bfloat16 h, lo;
        bsplit(v, h, lo);
        size_t o = (size_t)(e0 + ty * 4 + j) * LSEQ + l0 + tx;
        vth[o] = h; vtl[o] = lo;
    }
}

// ===========================================================================
// Tensor-core flash attention, bf16 3-term (hi/lo split) arithmetic.
// Block = (head, 128 Q rows), 8 warps x 16-row slices, KV tile 64.
// Smem: 128B rows + 16B-chunk XOR swizzle (conflict-free ldmatrix).
// ===========================================================================
#define S_QH 0
#define S_QL 16384
#define S_KH 32768
#define S_KL 40960
#define S_VH 49152
#define S_VL 57344
#define S_PH 65536
#define S_PL 81920
#define ATT_SMEM 98304

__global__ __launch_bounds__(256) void attn_mma(
    const __nv_bfloat16* __restrict__ qh_g, const __nv_bfloat16* __restrict__ ql_g,
    const __nv_bfloat16* __restrict__ kh_g, const __nv_bfloat16* __restrict__ kl_g,
    const __nv_bfloat16* __restrict__ vth_g, const __nv_bfloat16* __restrict__ vtl_g,
    float* __restrict__ out) {
    extern __shared__ char sm[];
    const uint32_t sb = smem_u32(sm);
    const int tid = threadIdx.x;
    const int t = tid & 31, w = tid >> 5;
    const int h = blockIdx.y;
    const int q0 = blockIdx.x * 128;
    const int g = t >> 2, tg = t & 3;

    // ldmatrix per-thread address components
    const int a_rl = (t & 7) + ((t >> 3) & 1) * 8;      // A frag rows within 16
    const int a_cb = ((t >> 4) & 1) * 16;               // A frag k-half byte
    const int b_rl = ((t >> 4) & 1) * 8 + (t & 7);      // B frag rows within nf-pair (16)
    const int b_cb = ((t >> 3) & 1) * 16;               // B frag k-half byte

    // Load Q hi/lo into swizzled smem (once per block)
#pragma unroll
    for (int i = 0; i < 4; i++) {
        int slot = tid + i * 256;                        // 128 rows x 8 chunks
        int row = slot >> 3, ch = slot & 7;
        uint32_t dst = (uint32_t)(row * 128 + ((ch * 16) ^ ((row & 7) * 16)));
        size_t src = (size_t)(q0 + row) * EMB + h * 64 + ch * 8;
        *reinterpret_cast<float4*>(sm + S_QH + dst) = *reinterpret_cast<const float4*>(qh_g + src);
        *reinterpret_cast<float4*>(sm + S_QL + dst) = *reinterpret_cast<const float4*>(ql_g + src);
    }

    float m0 = -1e30f, m1 = -1e30f, l0 = 0.f, l1 = 0.f;
    float o[8][4];
#pragma unroll
    for (int nf = 0; nf < 8; nf++)
#pragma unroll
        for (int v = 0; v < 4; v++) o[nf][v] = 0.f;

    for (int kt = 0; kt < LSEQ / 64; kt++) {
        __syncthreads();   // previous tile's MMAs done before overwriting K/Vt
        const int kv0 = kt * 64;
#pragma unroll
        for (int i = 0; i < 2; i++) {
            int slot = tid + i * 256;                    // 64 rows x 8 chunks
            int row = slot >> 3, ch = slot & 7;
            uint32_t dst = (uint32_t)(row * 128 + ((ch * 16) ^ ((row & 7) * 16)));
            size_t ksrc = (size_t)(kv0 + row) * EMB + h * 64 + ch * 8;
            size_t vsrc = (size_t)(h * 64 + row) * LSEQ + kv0 + ch * 8;
            *reinterpret_cast<float4*>(sm + S_KH + dst) = *reinterpret_cast<const float4*>(kh_g + ksrc);
            *reinterpret_cast<float4*>(sm + S_KL + dst) = *reinterpret_cast<const float4*>(kl_g + ksrc);
            *reinterpret_cast<float4*>(sm + S_VH + dst) = *reinterpret_cast<const float4*>(vth_g + vsrc);
            *reinterpret_cast<float4*>(sm + S_VL + dst) = *reinterpret_cast<const float4*>(vtl_g + vsrc);
        }
        __syncthreads();

        // ---- S = Q K^T (3-term bf16) ----
        float s[8][4];
#pragma unroll
        for (int nf = 0; nf < 8; nf++)
#pragma unroll
            for (int v = 0; v < 4; v++) s[nf][v] = 0.f;

#pragma unroll
        for (int ks = 0; ks < 4; ks++) {
            int qrow = w * 16 + a_rl;
            uint32_t qaddr = sb + (uint32_t)(qrow * 128 + ((ks * 32 + a_cb) ^ ((qrow & 7) * 16)));
            uint32_t qh0, qh1, qh2, qh3, ql0, ql1, ql2, ql3;
            ldmatrix_x4(qh0, qh1, qh2, qh3, qaddr + S_QH);
            ldmatrix_x4(ql0, ql1, ql2, ql3, qaddr + S_QL);
#pragma unroll
            for (int p = 0; p < 4; p++) {
                int krow = p * 16 + b_rl;
                uint32_t kaddr = sb + (uint32_t)(krow * 128 + ((ks * 32 + b_cb) ^ ((krow & 7) * 16)));
                uint32_t kh0, kh1, kh2, kh3, klo0, klo1, klo2, klo3;
                ldmatrix_x4(kh0, kh1, kh2, kh3, kaddr + S_KH);
                ldmatrix_x4(klo0, klo1, klo2, klo3, kaddr + S_KL);
                mma_bf16(s[2 * p], qh0, qh1, qh2, qh3, kh0, kh1);
                mma_bf16(s[2 * p], qh0, qh1, qh2, qh3, klo0, klo1);
                mma_bf16(s[2 * p], ql0, ql1, ql2, ql3, kh0, kh1);
                mma_bf16(s[2 * p + 1], qh0, qh1, qh2, qh3, kh2, kh3);
                mma_bf16(s[2 * p + 1], qh0, qh1, qh2, qh3, klo2, klo3);
                mma_bf16(s[2 * p + 1], ql0, ql1, ql2, ql3, kh2, kh3);
            }
        }

        // ---- online softmax (rows g and g+8, quad-owned) ----
        float mx0 = -1e30f, mx1 = -1e30f;
#pragma unroll
        for (int nf = 0; nf < 8; nf++) {
            mx0 = fmaxf(mx0, fmaxf(s[nf][0], s[nf][1]));
            mx1 = fmaxf(mx1, fmaxf(s[nf][2], s[nf][3]));
        }
        mx0 = fmaxf(mx0, __shfl_xor_sync(0xffffffffu, mx0, 1));
        mx0 = fmaxf(mx0, __shfl_xor_sync(0xffffffffu, mx0, 2));
        mx1 = fmaxf(mx1, __shfl_xor_sync(0xffffffffu, mx1, 1));
        mx1 = fmaxf(mx1, __shfl_xor_sync(0xffffffffu, mx1, 2));
        float mn0 = fmaxf(m0, mx0), mn1 = fmaxf(m1, mx1);
        float cr0 = __expf(m0 - mn0), cr1 = __expf(m1 - mn1);
        float sum0 = 0.f, sum1 = 0.f;
#pragma unroll
        for (int nf = 0; nf < 8; nf++) {
            s[nf][0] = __expf(s[nf][0] - mn0);
            s[nf][1] = __expf(s[nf][1] - mn0);
            s[nf][2] = __expf(s[nf][2] - mn1);
            s[nf][3] = __expf(s[nf][3] - mn1);
            sum0 += s[nf][0] + s[nf][1];
            sum1 += s[nf][2] + s[nf][3];
        }
        sum0 += __shfl_xor_sync(0xffffffffu, sum0, 1);
        sum0 += __shfl_xor_sync(0xffffffffu, sum0, 2);
        sum1 += __shfl_xor_sync(0xffffffffu, sum1, 1);
        sum1 += __shfl_xor_sync(0xffffffffu, sum1, 2);
        l0 = l0 * cr0 + sum0; m0 = mn0;
        l1 = l1 * cr1 + sum1; m1 = mn1;
#pragma unroll
        for (int nf = 0; nf < 8; nf++) {
            o[nf][0] *= cr0; o[nf][1] *= cr0;
            o[nf][2] *= cr1; o[nf][3] *= cr1;
        }

        // ---- store P (bf16 hi/lo) to smem, per-warp rows only ----
        {
            int r0 = w * 16 + g, r1 = r0 + 8;
#pragma unroll
            for (int nf = 0; nf < 8; nf++) {
                uint32_t a0 = (uint32_t)(r0 * 128 + ((nf * 16) ^ ((r0 & 7) * 16)) + tg * 4);
                uint32_t a1 = (uint32_t)(r1 * 128 + ((nf * 16) ^ ((r1 & 7) * 16)) + tg * 4);
                uint32_t phi, plo;
                bsplit2(s[nf][0], s[nf][1], phi, plo);
                *reinterpret_cast<uint32_t*>(sm + S_PH + a0) = phi;
                *reinterpret_cast<uint32_t*>(sm + S_PL + a0) = plo;
                bsplit2(s[nf][2], s[nf][3], phi, plo);
                *reinterpret_cast<uint32_t*>(sm + S_PH + a1) = phi;
                *reinterpret_cast<uint32_t*>(sm + S_PL + a1) = plo;
            }
        }
        __syncwarp();

        // ---- O += P V (3-term bf16) ----
#pragma unroll
        for (int ks = 0; ks < 4; ks++) {
            int prow = w * 16 + a_rl;
            uint32_t paddr = sb + (uint32_t)(prow * 128 + ((ks * 32 + a_cb) ^ ((prow & 7) * 16)));
            uint32_t ph0, ph1, ph2, ph3, pl0, pl1, pl2, pl3;
            ldmatrix_x4(ph0, ph1, ph2, ph3, paddr + S_PH);
            ldmatrix_x4(pl0, pl1, pl2, pl3, paddr + S_PL);
#pragma unroll
            for (int p = 0; p < 4; p++) {
                int vrow = p * 16 + b_rl;
                uint32_t vaddr = sb + (uint32_t)(vrow * 128 + ((ks * 32 + b_cb) ^ ((vrow & 7) * 16)));
                uint32_t vh0, vh1, vh2, vh3, vl0, vl1, vl2, vl3;
                ldmatrix_x4(vh0, vh1, vh2, vh3, vaddr + S_VH);
                ldmatrix_x4(vl0, vl1, vl2, vl3, vaddr + S_VL);
                mma_bf16(o[2 * p], ph0, ph1, ph2, ph3, vh0, vh1);
                mma_bf16(o[2 * p], ph0, ph1, ph2, ph3, vl0, vl1);
                mma_bf16(o[2 * p], pl0, pl1, pl2, pl3, vh0, vh1);
                mma_bf16(o[2 * p + 1], ph0, ph1, ph2, ph3, vh2, vh3);
                mma_bf16(o[2 * p + 1], ph0, ph1, ph2, ph3, vl2, vl3);
                mma_bf16(o[2 * p + 1], pl0, pl1, pl2, pl3, vh2, vh3);
            }
        }
    }

    // ---- epilogue ----
    float inv0 = 1.0f / l0, inv1 = 1.0f / l1;
    int row0 = q0 + w * 16 + g, row1 = row0 + 8;
#pragma unroll
    for (int nf = 0; nf < 8; nf++) {
        int col = h * 64 + nf * 8 + 2 * tg;
        *reinterpret_cast<float2*>(out + (size_t)row0 * EMB + col) =
            make_float2(o[nf][0] * inv0, o[nf][1] * inv0);
        *reinterpret_cast<float2*>(out + (size_t)row1 * EMB + col) =
            make_float2(o[nf][2] * inv1, o[nf][3] * inv1);
    }
}

// ===========================================================================
extern "C" void kernel_launch(void* const* d_in, const int* in_sizes, int n_in,
                              void* d_out, int out_size) {
    const float* x     = (const float*)d_in[0];   // [L, 1, E]
    const float* w_qkv = (const float*)d_in[1];   // [3E, E]
    const float* w_out = (const float*)d_in[2];   // [E, E]
    float* out = (float*)d_out;                   // [L, 1, E]

    float *qkv, *attn;
    __nv_bfloat16 *qh, *ql, *kh, *kl, *vth, *vtl;
    cudaGetSymbolAddress((void**)&qkv, g_qkv);
    cudaGetSymbolAddress((void**)&attn, g_attn);
    cudaGetSymbolAddress((void**)&qh, g_qh);
    cudaGetSymbolAddress((void**)&ql, g_ql);
    cudaGetSymbolAddress((void**)&kh, g_kh);
    cudaGetSymbolAddress((void**)&kl, g_kl);
    cudaGetSymbolAddress((void**)&vth, g_vth);
    cudaGetSymbolAddress((void**)&vtl, g_vtl);

    cudaFuncSetAttribute(attn_mma, cudaFuncAttributeMaxDynamicSharedMemorySize, ATT_SMEM);

    // 1) QKV projection: [L,E] @ [3E,E]^T -> [L,3E]  (mma.sync tf32)
    gemm_mma<<<dim3(QKV3 / 128, LSEQ / 128), 256>>>(x, w_qkv, qkv, LSEQ, QKV3, EMB);

    // 2) Prep: bf16 hi/lo splits (+ V transpose)
    prep_qk<<<(LSEQ * EMB / 4) / 256, 256>>>(qkv, qh, ql, kh, kl);
    prep_vt<<<dim3(EMB / 32, LSEQ / 32), dim3(32, 8)>>>(qkv, vth, vtl);

    // 3) Attention (mma.sync bf16 3-term, flash)
    attn_mma<<<dim3(LSEQ / 128, NH), 256, ATT_SMEM>>>(qh, ql, kh, kl, vth, vtl, attn);

    // 4) Output projection: [L,E] @ [E,E]^T -> [L,E]  (mma.sync tf32)
    gemm_mma<<<dim3(EMB / 128, LSEQ / 128), 256>>>(attn, w_out, out, LSEQ, EMB, EMB);
}

// round 9
// speedup vs baseline: 4.9173x; 1.1611x over previous
#include <cuda_runtime.h>
#include <cuda_bf16.h>
#include <cstdint>
#include <math.h>

#define LSEQ 4096
#define EMB  1024
#define NH   16
#define DH   64
#define QKV3 3072

// Scratch (allocation-free rule: device globals)
__device__ float g_qkv[LSEQ * QKV3];   // [L, 3E]
__device__ float g_attn[LSEQ * EMB];   // [L, E]
__device__ __nv_bfloat16 g_qh[LSEQ * EMB], g_ql[LSEQ * EMB];   // Q*scale hi/lo [L,E]
__device__ __nv_bfloat16 g_kh[LSEQ * EMB], g_kl[LSEQ * EMB];   // K hi/lo [L,E]
__device__ __nv_bfloat16 g_vth[EMB * LSEQ], g_vtl[EMB * LSEQ]; // V^T hi/lo [E,L]

// ===========================================================================
// PTX helpers (non-'a' features only: ldmatrix / mma.sync / cp.async / cvt)
// ===========================================================================
__device__ __forceinline__ uint32_t smem_u32(const void* p) {
    uint32_t a;
    asm("{ .reg .u64 t; cvta.to.shared.u64 t, %1; cvt.u32.u64 %0, t; }" : "=r"(a) : "l"(p));
    return a;
}
__device__ __forceinline__ uint32_t f2tf32(float f) {
    uint32_t r; asm("cvt.rna.tf32.f32 %0, %1;" : "=r"(r) : "f"(f)); return r;
}
__device__ __forceinline__ void ldmatrix_x4(uint32_t& r0, uint32_t& r1, uint32_t& r2, uint32_t& r3,
                                            uint32_t addr) {
    asm volatile("ldmatrix.sync.aligned.m8n8.x4.shared.b16 {%0,%1,%2,%3}, [%4];"
                 : "=r"(r0), "=r"(r1), "=r"(r2), "=r"(r3) : "r"(addr));
}
__device__ __forceinline__ void ldmatrix_x2(uint32_t& r0, uint32_t& r1, uint32_t addr) {
    asm volatile("ldmatrix.sync.aligned.m8n8.x2.shared.b16 {%0,%1}, [%2];"
                 : "=r"(r0), "=r"(r1) : "r"(addr));
}
__device__ __forceinline__ void mma_tf32(float& c0, float& c1, float& c2, float& c3,
                                         uint32_t a0, uint32_t a1, uint32_t a2, uint32_t a3,
                                         uint32_t b0, uint32_t b1) {
    asm volatile(
        "mma.sync.aligned.m16n8k8.row.col.f32.tf32.tf32.f32 "
        "{%0,%1,%2,%3}, {%4,%5,%6,%7}, {%8,%9}, {%0,%1,%2,%3};"
        : "+f"(c0), "+f"(c1), "+f"(c2), "+f"(c3)
        : "r"(a0), "r"(a1), "r"(a2), "r"(a3), "r"(b0), "r"(b1));
}
__device__ __forceinline__ void mma_bf16(float* c,
                                         uint32_t a0, uint32_t a1, uint32_t a2, uint32_t a3,
                                         uint32_t b0, uint32_t b1) {
    asm volatile(
        "mma.sync.aligned.m16n8k16.row.col.f32.bf16.bf16.f32 "
        "{%0,%1,%2,%3}, {%4,%5,%6,%7}, {%8,%9}, {%0,%1,%2,%3};"
        : "+f"(c[0]), "+f"(c[1]), "+f"(c[2]), "+f"(c[3])
        : "r"(a0), "r"(a1), "r"(a2), "r"(a3), "r"(b0), "r"(b1));
}
__device__ __forceinline__ void bsplit(float x, __nv_bfloat16& h, __nv_bfloat16& l) {
    h = __float2bfloat16(x);
    l = __float2bfloat16(x - __bfloat162float(h));
}
__device__ __forceinline__ void bsplit2(float x0, float x1, uint32_t& hi, uint32_t& lo) {
    __nv_bfloat16 h0, l0, h1, l1;
    bsplit(x0, h0, l0);
    bsplit(x1, h1, l1);
    hi = ((uint32_t)__bfloat16_as_ushort(h1) << 16) | (uint32_t)__bfloat16_as_ushort(h0);
    lo = ((uint32_t)__bfloat16_as_ushort(l1) << 16) | (uint32_t)__bfloat16_as_ushort(l0);
}
__device__ __forceinline__ void cp16(uint32_t dst, const void* src) {
    asm volatile("cp.async.cg.shared.global [%0], [%1], 16;" :: "r"(dst), "l"(src));
}
__device__ __forceinline__ void cp_commit() {
    asm volatile("cp.async.commit_group;" ::: "memory");
}
template <int N>
__device__ __forceinline__ void cp_wait() {
    asm volatile("cp.async.wait_group %0;" :: "n"(N) : "memory");
}

// ===========================================================================
// Tensor-core tf32 GEMM (unchanged): C[m][n] = sum_k A[m][k]*B[n][k]
// ===========================================================================
#define GPAD 36

__global__ __launch_bounds__(256) void gemm_mma(const float* __restrict__ A,
                                                const float* __restrict__ B,
                                                float* __restrict__ C,
                                                int M, int N, int K) {
    __shared__ float As[128 * GPAD];
    __shared__ float Bs[128 * GPAD];

    const int tid = threadIdx.x;
    const int t = tid & 31;
    const int wid = tid >> 5;
    const int wm = wid >> 2;
    const int wn = wid & 3;
    const int rbase = blockIdx.y * 128;
    const int cbase = blockIdx.x * 128;
    const int nchunks = K >> 5;

    const uint32_t As_b = smem_u32(As);
    const uint32_t Bs_b = smem_u32(Bs);

    const int a_rl = (t & 7) + ((t >> 3) & 1) * 8;
    const int a_cb = ((t >> 4) & 1) * 16;
    const int b_rl = (t & 7);
    const int b_cb = ((t >> 3) & 1) * 16;

    float c[4][4][4];
#pragma unroll
    for (int mf = 0; mf < 4; mf++)
#pragma unroll
        for (int nf = 0; nf < 4; nf++)
#pragma unroll
            for (int v = 0; v < 4; v++) c[mf][nf][v] = 0.f;

    float4 pa[4], pb[4];
    {
        const float* Ag = A + (size_t)rbase * K;
        const float* Bg = B + (size_t)cbase * K;
#pragma unroll
        for (int i = 0; i < 4; i++) {
            int fi = tid + i * 256;
            int row = fi >> 3, c4 = (fi & 7) << 2;
            pa[i] = *reinterpret_cast<const float4*>(Ag + (size_t)row * K + c4);
            pb[i] = *reinterpret_cast<const float4*>(Bg + (size_t)row * K + c4);
        }
    }

    for (int ck = 0; ck < nchunks; ck++) {
#pragma unroll
        for (int i = 0; i < 4; i++) {
            int fi = tid + i * 256;
            int row = fi >> 3, c4 = (fi & 7) << 2;
            float4 av, bv;
            av.x = __uint_as_float(f2tf32(pa[i].x));
            av.y = __uint_as_float(f2tf32(pa[i].y));
            av.z = __uint_as_float(f2tf32(pa[i].z));
            av.w = __uint_as_float(f2tf32(pa[i].w));
            bv.x = __uint_as_float(f2tf32(pb[i].x));
            bv.y = __uint_as_float(f2tf32(pb[i].y));
            bv.z = __uint_as_float(f2tf32(pb[i].z));
            bv.w = __uint_as_float(f2tf32(pb[i].w));
            *reinterpret_cast<float4*>(&As[row * GPAD + c4]) = av;
            *reinterpret_cast<float4*>(&Bs[row * GPAD + c4]) = bv;
        }
        __syncthreads();

        if (ck + 1 < nchunks) {
            const float* Ag = A + (size_t)rbase * K + (ck + 1) * 32;
            const float* Bg = B + (size_t)cbase * K + (ck + 1) * 32;
#pragma unroll
            for (int i = 0; i < 4; i++) {
                int fi = tid + i * 256;
                int row = fi >> 3, c4 = (fi & 7) << 2;
                pa[i] = *reinterpret_cast<const float4*>(Ag + (size_t)row * K + c4);
                pb[i] = *reinterpret_cast<const float4*>(Bg + (size_t)row * K + c4);
            }
        }

#pragma unroll
        for (int ks = 0; ks < 4; ks++) {
            uint32_t af[4][4], bf[4][2];
#pragma unroll
            for (int mf = 0; mf < 4; mf++) {
                int row = wm * 64 + mf * 16 + a_rl;
                uint32_t addr = As_b + (uint32_t)(row * GPAD * 4 + ks * 32 + a_cb);
                ldmatrix_x4(af[mf][0], af[mf][1], af[mf][2], af[mf][3], addr);
            }
#pragma unroll
            for (int nf = 0; nf < 4; nf++) {
                int row = wn * 32 + nf * 8 + b_rl;
                uint32_t addr = Bs_b + (uint32_t)(row * GPAD * 4 + ks * 32 + b_cb);
                ldmatrix_x2(bf[nf][0], bf[nf][1], addr);
            }
#pragma unroll
            for (int mf = 0; mf < 4; mf++)
#pragma unroll
                for (int nf = 0; nf < 4; nf++)
                    mma_tf32(c[mf][nf][0], c[mf][nf][1], c[mf][nf][2], c[mf][nf][3],
                             af[mf][0], af[mf][1], af[mf][2], af[mf][3],
                             bf[nf][0], bf[nf][1]);
        }
        __syncthreads();
    }

    const int g = t >> 2;
    const int tg = t & 3;
#pragma unroll
    for (int mf = 0; mf < 4; mf++) {
        int row0 = rbase + wm * 64 + mf * 16 + g;
#pragma unroll
        for (int nf = 0; nf < 4; nf++) {
            int col = cbase + wn * 32 + nf * 8 + 2 * tg;
            float2 lo = make_float2(c[mf][nf][0], c[mf][nf][1]);
            float2 hi = make_float2(c[mf][nf][2], c[mf][nf][3]);
            *reinterpret_cast<float2*>(&C[(size_t)row0 * N + col]) = lo;
            *reinterpret_cast<float2*>(&C[(size_t)(row0 + 8) * N + col]) = hi;
        }
    }
}

// ===========================================================================
// Prep kernels (unchanged)
// ===========================================================================
__global__ __launch_bounds__(256) void prep_qk(const float* __restrict__ qkv,
                                               __nv_bfloat16* __restrict__ qh,
                                               __nv_bfloat16* __restrict__ ql,
                                               __nv_bfloat16* __restrict__ kh,
                                               __nv_bfloat16* __restrict__ kl) {
    int idx = blockIdx.x * 256 + threadIdx.x;
    int l = idx >> 8;
    int e = (idx & 255) << 2;
    float4 q = *reinterpret_cast<const float4*>(qkv + (size_t)l * QKV3 + e);
    float4 k = *reinterpret_cast<const float4*>(qkv + (size_t)l * QKV3 + EMB + e);
    size_t o = (size_t)l * EMB + e;
    float qs[4] = {q.x * 0.125f, q.y * 0.125f, q.z * 0.125f, q.w * 0.125f};
    float ks[4] = {k.x, k.y, k.z, k.w};
#pragma unroll
    for (int j = 0; j < 4; j++) {
        __nv_bfloat16 h, lo;
        bsplit(qs[j], h, lo);
        qh[o + j] = h; ql[o + j] = lo;
        bsplit(ks[j], h, lo);
        kh[o + j] = h; kl[o + j] = lo;
    }
}

__global__ __launch_bounds__(256) void prep_vt(const float* __restrict__ qkv,
                                               __nv_bfloat16* __restrict__ vth,
                                               __nv_bfloat16* __restrict__ vtl) {
    __shared__ float tile[32][33];
    const int e0 = blockIdx.x * 32;
    const int l0 = blockIdx.y * 32;
    const int tx = threadIdx.x, ty = threadIdx.y;
#pragma unroll
    for (int j = 0; j < 4; j++)
        tile[ty * 4 + j][tx] = qkv[(size_t)(l0 + ty * 4 + j) * QKV3 + 2 * EMB + e0 + tx];
    __syncthreads();
#pragma unroll
    for (int j = 0; j < 4; j++) {
        float v = tile[tx][ty * 4 + j];
        __nv_bfloat16 h, lo;
        bsplit(v, h, lo);
        size_t o = (size_t)(e0 + ty * 4 + j) * LSEQ + l0 + tx;
        vth[o] = h; vtl[o] = lo;
    }
}

// ===========================================================================
// Flash attention v3: 4 warps x 32 Q rows (128-row tile), register-resident P,
// cp.async double-buffered KV tiles. bf16 3-term arithmetic throughout.
// Smem: QH 16K | QL 16K | 2 x (KH 8K | KL 8K | VH 8K | VL 8K) = 96KB.
// ===========================================================================
#define S_QL_OFF 16384
#define KV_OFF   32768
#define KV_STRIDE 32768
#define KL_OFF   8192
#define V_OFF    16384
#define VL_OFF   8192
#define ATT_SMEM 98304

__global__ __launch_bounds__(128) void attn_mma(
    const __nv_bfloat16* __restrict__ qh_g, const __nv_bfloat16* __restrict__ ql_g,
    const __nv_bfloat16* __restrict__ kh_g, const __nv_bfloat16* __restrict__ kl_g,
    const __nv_bfloat16* __restrict__ vth_g, const __nv_bfloat16* __restrict__ vtl_g,
    float* __restrict__ out) {
    extern __shared__ char sm[];
    const uint32_t sb = smem_u32(sm);
    const int tid = threadIdx.x;
    const int t = tid & 31, w = tid >> 5;
    const int h = blockIdx.y;
    const int q0 = blockIdx.x * 128;
    const int g = t >> 2, tg = t & 3;

    const int a_rl = (t & 7) + ((t >> 3) & 1) * 8;
    const int a_cb = ((t >> 4) & 1) * 16;
    const int b_rl = ((t >> 4) & 1) * 8 + (t & 7);
    const int b_cb = ((t >> 3) & 1) * 16;

    // ---- issue Q loads (cp.async), 128 rows x 8 chunks, hi+lo ----
#pragma unroll
    for (int i = 0; i < 8; i++) {
        int slot = tid + i * 128;
        int row = slot >> 3, ch = slot & 7;
        uint32_t dst = (uint32_t)(row * 128 + ((ch * 16) ^ ((row & 7) * 16)));
        size_t src = (size_t)(q0 + row) * EMB + h * 64 + ch * 8;
        cp16(sb + dst, qh_g + src);
        cp16(sb + S_QL_OFF + dst, ql_g + src);
    }
    // ---- issue KV tile 0 ----
#pragma unroll
    for (int i = 0; i < 4; i++) {
        int slot = tid + i * 128;
        int row = slot >> 3, ch = slot & 7;
        uint32_t dst = (uint32_t)(row * 128 + ((ch * 16) ^ ((row & 7) * 16)));
        size_t ksrc = (size_t)row * EMB + h * 64 + ch * 8;
        size_t vsrc = (size_t)(h * 64 + row) * LSEQ + ch * 8;
        uint32_t kb = sb + KV_OFF;
        cp16(kb + dst, kh_g + ksrc);
        cp16(kb + KL_OFF + dst, kl_g + ksrc);
        cp16(kb + V_OFF + dst, vth_g + vsrc);
        cp16(kb + V_OFF + VL_OFF + dst, vtl_g + vsrc);
    }
    cp_commit();

    float m_st[4], l_st[4];
#pragma unroll
    for (int i = 0; i < 4; i++) { m_st[i] = -1e30f; l_st[i] = 0.f; }
    float o[2][8][4];
#pragma unroll
    for (int mf = 0; mf < 2; mf++)
#pragma unroll
        for (int nf = 0; nf < 8; nf++)
#pragma unroll
            for (int v = 0; v < 4; v++) o[mf][nf][v] = 0.f;

    const int NT = LSEQ / 64;
    for (int kt = 0; kt < NT; kt++) {
        const int b = kt & 1;
        const uint32_t kvb = sb + KV_OFF + b * KV_STRIDE;

        // issue next tile into other buffer (safe: prev compute of that buffer
        // finished before last iteration's trailing __syncthreads)
        if (kt + 1 < NT) {
            const int kv1 = (kt + 1) * 64;
            const uint32_t nb = sb + KV_OFF + (b ^ 1) * KV_STRIDE;
#pragma unroll
            for (int i = 0; i < 4; i++) {
                int slot = tid + i * 128;
                int row = slot >> 3, ch = slot & 7;
                uint32_t dst = (uint32_t)(row * 128 + ((ch * 16) ^ ((row & 7) * 16)));
                size_t ksrc = (size_t)(kv1 + row) * EMB + h * 64 + ch * 8;
                size_t vsrc = (size_t)(h * 64 + row) * LSEQ + kv1 + ch * 8;
                cp16(nb + dst, kh_g + ksrc);
                cp16(nb + KL_OFF + dst, kl_g + ksrc);
                cp16(nb + V_OFF + dst, vth_g + vsrc);
                cp16(nb + V_OFF + VL_OFF + dst, vtl_g + vsrc);
            }
            cp_commit();
            cp_wait<1>();   // drain current tile's group (next may stay in flight)
        } else {
            cp_wait<0>();
        }
        __syncthreads();

        // ---- S = Q K^T (3-term bf16), warp rows = w*32 .. +31 ----
        float s[2][8][4];
#pragma unroll
        for (int mf = 0; mf < 2; mf++)
#pragma unroll
            for (int nf = 0; nf < 8; nf++)
#pragma unroll
                for (int v = 0; v < 4; v++) s[mf][nf][v] = 0.f;

#pragma unroll
        for (int ks = 0; ks < 4; ks++) {
            uint32_t qh_f[2][4], ql_f[2][4];
#pragma unroll
            for (int mf = 0; mf < 2; mf++) {
                int qrow = w * 32 + mf * 16 + a_rl;
                uint32_t qaddr = sb + (uint32_t)(qrow * 128 + ((ks * 32 + a_cb) ^ ((qrow & 7) * 16)));
                ldmatrix_x4(qh_f[mf][0], qh_f[mf][1], qh_f[mf][2], qh_f[mf][3], qaddr);
                ldmatrix_x4(ql_f[mf][0], ql_f[mf][1], ql_f[mf][2], ql_f[mf][3], qaddr + S_QL_OFF);
            }
#pragma unroll
            for (int p = 0; p < 4; p++) {
                int krow = p * 16 + b_rl;
                uint32_t kaddr = kvb + (uint32_t)(krow * 128 + ((ks * 32 + b_cb) ^ ((krow & 7) * 16)));
                uint32_t kh0, kh1, kh2, kh3, klo0, klo1, klo2, klo3;
                ldmatrix_x4(kh0, kh1, kh2, kh3, kaddr);
                ldmatrix_x4(klo0, klo1, klo2, klo3, kaddr + KL_OFF);
#pragma unroll
                for (int mf = 0; mf < 2; mf++) {
                    mma_bf16(s[mf][2 * p], qh_f[mf][0], qh_f[mf][1], qh_f[mf][2], qh_f[mf][3], kh0, kh1);
                    mma_bf16(s[mf][2 * p], qh_f[mf][0], qh_f[mf][1], qh_f[mf][2], qh_f[mf][3], klo0, klo1);
                    mma_bf16(s[mf][2 * p], ql_f[mf][0], ql_f[mf][1], ql_f[mf][2], ql_f[mf][3], kh0, kh1);
                    mma_bf16(s[mf][2 * p + 1], qh_f[mf][0], qh_f[mf][1], qh_f[mf][2], qh_f[mf][3], kh2, kh3);
                    mma_bf16(s[mf][2 * p + 1], qh_f[mf][0], qh_f[mf][1], qh_f[mf][2], qh_f[mf][3], klo2, klo3);
                    mma_bf16(s[mf][2 * p + 1], ql_f[mf][0], ql_f[mf][1], ql_f[mf][2], ql_f[mf][3], kh2, kh3);
                }
            }
        }

        // ---- online softmax (4 row-states: mf x {g, g+8}) ----
#pragma unroll
        for (int mf = 0; mf < 2; mf++) {
            float mx0 = -1e30f, mx1 = -1e30f;
#pragma unroll
            for (int nf = 0; nf < 8; nf++) {
                mx0 = fmaxf(mx0, fmaxf(s[mf][nf][0], s[mf][nf][1]));
                mx1 = fmaxf(mx1, fmaxf(s[mf][nf][2], s[mf][nf][3]));
            }
            mx0 = fmaxf(mx0, __shfl_xor_sync(0xffffffffu, mx0, 1));
            mx0 = fmaxf(mx0, __shfl_xor_sync(0xffffffffu, mx0, 2));
            mx1 = fmaxf(mx1, __shfl_xor_sync(0xffffffffu, mx1, 1));
            mx1 = fmaxf(mx1, __shfl_xor_sync(0xffffffffu, mx1, 2));
            float mn0 = fmaxf(m_st[mf * 2 + 0], mx0);
            float mn1 = fmaxf(m_st[mf * 2 + 1], mx1);
            float cr0 = __expf(m_st[mf * 2 + 0] - mn0);
            float cr1 = __expf(m_st[mf * 2 + 1] - mn1);
            float sum0 = 0.f, sum1 = 0.f;
#pragma unroll
            for (int nf = 0; nf < 8; nf++) {
                s[mf][nf][0] = __expf(s[mf][nf][0] - mn0);
                s[mf][nf][1] = __expf(s[mf][nf][1] - mn0);
                s[mf][nf][2] = __expf(s[mf][nf][2] - mn1);
                s[mf][nf][3] = __expf(s[mf][nf][3] - mn1);
                sum0 += s[mf][nf][0] + s[mf][nf][1];
                sum1 += s[mf][nf][2] + s[mf][nf][3];
            }
            sum0 += __shfl_xor_sync(0xffffffffu, sum0, 1);
            sum0 += __shfl_xor_sync(0xffffffffu, sum0, 2);
            sum1 += __shfl_xor_sync(0xffffffffu, sum1, 1);
            sum1 += __shfl_xor_sync(0xffffffffu, sum1, 2);
            l_st[mf * 2 + 0] = l_st[mf * 2 + 0] * cr0 + sum0;
            l_st[mf * 2 + 1] = l_st[mf * 2 + 1] * cr1 + sum1;
            m_st[mf * 2 + 0] = mn0;
            m_st[mf * 2 + 1] = mn1;
#pragma unroll
            for (int nf = 0; nf < 8; nf++) {
                o[mf][nf][0] *= cr0; o[mf][nf][1] *= cr0;
                o[mf][nf][2] *= cr1; o[mf][nf][3] *= cr1;
            }
        }

        // ---- O += P V, P taken straight from S registers (no smem) ----
#pragma unroll
        for (int ks = 0; ks < 4; ks++) {
            uint32_t ah[2][4], al[2][4];
#pragma unroll
            for (int mf = 0; mf < 2; mf++) {
                bsplit2(s[mf][2 * ks][0], s[mf][2 * ks][1], ah[mf][0], al[mf][0]);
                bsplit2(s[mf][2 * ks][2], s[mf][2 * ks][3], ah[mf][1], al[mf][1]);
                bsplit2(s[mf][2 * ks + 1][0], s[mf][2 * ks + 1][1], ah[mf][2], al[mf][2]);
                bsplit2(s[mf][2 * ks + 1][2], s[mf][2 * ks + 1][3], ah[mf][3], al[mf][3]);
            }
#pragma unroll
            for (int p = 0; p < 4; p++) {
                int vrow = p * 16 + b_rl;
                uint32_t vaddr = kvb + V_OFF +
                    (uint32_t)(vrow * 128 + ((ks * 32 + b_cb) ^ ((vrow & 7) * 16)));
                uint32_t vh0, vh1, vh2, vh3, vl0, vl1, vl2, vl3;
                ldmatrix_x4(vh0, vh1, vh2, vh3, vaddr);
                ldmatrix_x4(vl0, vl1, vl2, vl3, vaddr + VL_OFF);
#pragma unroll
                for (int mf = 0; mf < 2; mf++) {
                    mma_bf16(o[mf][2 * p], ah[mf][0], ah[mf][1], ah[mf][2], ah[mf][3], vh0, vh1);
                    mma_bf16(o[mf][2 * p], ah[mf][0], ah[mf][1], ah[mf][2], ah[mf][3], vl0, vl1);
                    mma_bf16(o[mf][2 * p], al[mf][0], al[mf][1], al[mf][2], al[mf][3], vh0, vh1);
                    mma_bf16(o[mf][2 * p + 1], ah[mf][0], ah[mf][1], ah[mf][2], ah[mf][3], vh2, vh3);
                    mma_bf16(o[mf][2 * p + 1], ah[mf][0], ah[mf][1], ah[mf][2], ah[mf][3], vl2, vl3);
                    mma_bf16(o[mf][2 * p + 1], al[mf][0], al[mf][1], al[mf][2], al[mf][3], vh2, vh3);
                }
            }
        }
        __syncthreads();   // compute done before buf[b] reused at kt+2's issue
    }

    // ---- epilogue ----
#pragma unroll
    for (int mf = 0; mf < 2; mf++) {
        float inv0 = 1.0f / l_st[mf * 2 + 0];
        float inv1 = 1.0f / l_st[mf * 2 + 1];
        int row0 = q0 + w * 32 + mf * 16 + g;
        int row1 = row0 + 8;
#pragma unroll
        for (int nf = 0; nf < 8; nf++) {
            int col = h * 64 + nf * 8 + 2 * tg;
            *reinterpret_cast<float2*>(out + (size_t)row0 * EMB + col) =
                make_float2(o[mf][nf][0] * inv0, o[mf][nf][1] * inv0);
            *reinterpret_cast<float2*>(out + (size_t)row1 * EMB + col) =
                make_float2(o[mf][nf][2] * inv1, o[mf][nf][3] * inv1);
        }
    }
}

// ===========================================================================
extern "C" void kernel_launch(void* const* d_in, const int* in_sizes, int n_in,
                              void* d_out, int out_size) {
    const float* x     = (const float*)d_in[0];   // [L, 1, E]
    const float* w_qkv = (const float*)d_in[1];   // [3E, E]
    const float* w_out = (const float*)d_in[2];   // [E, E]
    float* out = (float*)d_out;                   // [L, 1, E]

    float *qkv, *attn;
    __nv_bfloat16 *qh, *ql, *kh, *kl, *vth, *vtl;
    cudaGetSymbolAddress((void**)&qkv, g_qkv);
    cudaGetSymbolAddress((void**)&attn, g_attn);
    cudaGetSymbolAddress((void**)&qh, g_qh);
    cudaGetSymbolAddress((void**)&ql, g_ql);
    cudaGetSymbolAddress((void**)&kh, g_kh);
    cudaGetSymbolAddress((void**)&kl, g_kl);
    cudaGetSymbolAddress((void**)&vth, g_vth);
    cudaGetSymbolAddress((void**)&vtl, g_vtl);

    cudaFuncSetAttribute(attn_mma, cudaFuncAttributeMaxDynamicSharedMemorySize, ATT_SMEM);

    // 1) QKV projection: [L,E] @ [3E,E]^T -> [L,3E]  (mma.sync tf32)
    gemm_mma<<<dim3(QKV3 / 128, LSEQ / 128), 256>>>(x, w_qkv, qkv, LSEQ, QKV3, EMB);

    // 2) Prep: bf16 hi/lo splits (+ V transpose)
    prep_qk<<<(LSEQ * EMB / 4) / 256, 256>>>(qkv, qh, ql, kh, kl);
    prep_vt<<<dim3(EMB / 32, LSEQ / 32), dim3(32, 8)>>>(qkv, vth, vtl);

    // 3) Attention (mma.sync bf16 3-term, register-resident P, cp.async pipe)
    attn_mma<<<dim3(LSEQ / 128, NH), 128, ATT_SMEM>>>(qh, ql, kh, kl, vth, vtl, attn);

    // 4) Output projection: [L,E] @ [E,E]^T -> [L,E]  (mma.sync tf32)
    gemm_mma<<<dim3(EMB / 128, LSEQ / 128), 256>>>(attn, w_out, out, LSEQ, EMB, EMB);
}